// round 10
// baseline (speedup 1.0000x reference)
#include <cuda_runtime.h>
#include <cuda_pipeline.h>

// ScaledPLLayer: persistence landscape from precomputed PH pairs.
//   x: [B=64, HW=4096] f32; birth_loc/death_loc/dim_idx: [B,128] i32
//   out: [B, 2, T=100, K=2] f32
//
// out[b,d,t,k] = k-th largest of {max(min(t-birth_n, death_n-t),0) : dim_n==d}
// == top-2 with 0-init over raw tent values of dim-d pairs (order-invariant).
//
// R9 = R5 skeleton (best measured: 6.176us) with cp.async staging:
//  - Phase 0 (parallel): all 512 threads stage the 16KB x-row into smem via
//    cp.async (LDGSTS: no register round-trip, fire-and-forget into SMEM);
//    warp 0 loads index arrays AND computes the full ballot partition
//    (positions/counts/sentinel padding — independent of gathered values,
//    fully overlapped with the staging latency).
//  - wait_prior(0); BAR1; warp 0: 8 pipelined LDS gathers + 4 scatter STS
//    into packed s0 (dim0) / s1 (dim1), padded to a 16-pair multiple with
//    sentinel (4,-4) (tent < 0 everywhere -> no-op under 0-init top-2).
//  - BAR2; octet of threads per t: float4 loads (2 pairs/LDS, broadcast,
//    conflict-free), dual accumulator pairs, exact trip counts.
//  - 3-round shfl_xor top-2 merge (measured best); sub 0 stores 2x float2.

#define B_    64
#define HW_   4096
#define NPH_  128
#define T_    100
#define TPC_  50
#define FULL_ 0xffffffffu

__device__ __forceinline__ void top2_ins(float v, float& m1, float& m2) {
    m2 = fmaxf(m2, fminf(m1, v));
    m1 = fmaxf(m1, v);
}
// merge sorted pair (h1>=h2) into (m1>=m2)
__device__ __forceinline__ void top2_merge(float h1, float h2, float& m1, float& m2) {
    m2 = fmaxf(fminf(m1, h1), fmaxf(m2, h2));
    m1 = fmaxf(m1, h1);
}

__global__ __launch_bounds__(512, 2)
void scaled_pl_kernel(const float* __restrict__ x,
                      const int*   __restrict__ bloc,
                      const int*   __restrict__ dloc,
                      const int*   __restrict__ didx,
                      float*       __restrict__ out) {
    __shared__ __align__(16) float  sx[HW_];        // 16 KB sample row
    __shared__ __align__(16) float2 s0[NPH_ + 16];  // dim0 value pairs
    __shared__ __align__(16) float2 s1[NPH_ + 16];  // dim1 value pairs
    __shared__ int s_n0r, s_n1r;

    const int b     = blockIdx.x >> 1;
    const int thalf = blockIdx.x & 1;
    const int tid   = threadIdx.x;

    // ---- phase 0a: stage x row via cp.async (all 512 threads, 2x 16B) ----
    {
        const float4* xb4 = (const float4*)(x + b * HW_);
        float4* sx4 = (float4*)sx;
        __pipeline_memcpy_async(&sx4[tid],       xb4 + tid,       16);
        __pipeline_memcpy_async(&sx4[tid + 512], xb4 + tid + 512, 16);
        __pipeline_commit();
    }

    // ---- phase 0b: warp 0 — index loads + FULL partition (no sx needed) ----
    int biv[4], div_[4], pos[4];
    bool is0f[4];
    if (tid < 32) {
        const int lane = tid;
        const int4 bi = __ldg((const int4*)(bloc + b * NPH_) + lane);
        const int4 di = __ldg((const int4*)(dloc + b * NPH_) + lane);
        const int4 dm = __ldg((const int4*)(didx + b * NPH_) + lane);
        biv[0] = bi.x; biv[1] = bi.y; biv[2] = bi.z; biv[3] = bi.w;
        div_[0] = di.x; div_[1] = di.y; div_[2] = di.z; div_[3] = di.w;
        const int dmv[4] = { dm.x, dm.y, dm.z, dm.w };

        const unsigned lt = (1u << lane) - 1u;
        int off0 = 0, off1 = 0;
        #pragma unroll
        for (int p = 0; p < 4; ++p) {
            const bool is0 = (dmv[p] == 0);
            const unsigned mb = __ballot_sync(FULL_, is0);
            const int c0 = __popc(mb);
            is0f[p] = is0;
            pos[p]  = is0 ? (off0 + __popc(mb & lt))
                          : (off1 + __popc(~mb & lt));
            off0 += c0;
            off1 += 32 - c0;
        }
        // sentinel padding to a multiple of 16 pairs (pre-BAR: pad slots are
        // disjoint from the value-scatter slots)
        const int n0r = (off0 + 15) & ~15;
        const int n1r = (off1 + 15) & ~15;
        if (off0 + lane < n0r) s0[off0 + lane] = make_float2(4.0f, -4.0f);
        if (off1 + lane < n1r) s1[off1 + lane] = make_float2(4.0f, -4.0f);
        if (lane == 0) { s_n0r = n0r; s_n1r = n1r; }
    }
    __pipeline_wait_prior(0);
    __syncthreads();

    // ---- phase 1: warp 0 — 8 pipelined LDS gathers + 4 scatters ----
    if (tid < 32) {
        float fb[4], fd[4];
        #pragma unroll
        for (int p = 0; p < 4; ++p) { fb[p] = sx[biv[p]]; fd[p] = sx[div_[p]]; }
        #pragma unroll
        for (int p = 0; p < 4; ++p) {
            (is0f[p] ? s0 : s1)[pos[p]] = make_float2(fb[p], fd[p]);
        }
    }
    __syncthreads();

    // ---- phase 2: octet per t, float4 loads, dual accumulators ----
    const int tl  = tid >> 3;            // 0..63
    const int sub = tid & 7;
    const int tg  = thalf * TPC_ + tl;
    const float t = (float)tg * (1.0f / (float)(T_ - 1));

    const int g0 = s_n0r >> 1;           // #float4 groups, multiple of 8
    const int g1 = s_n1r >> 1;
    const float4* v0 = (const float4*)s0;
    const float4* v1 = (const float4*)s1;

    float a1 = 0.f, a2 = 0.f, a3 = 0.f, a4 = 0.f;   // dim0 dual top-2
    float c1 = 0.f, c2 = 0.f, c3 = 0.f, c4 = 0.f;   // dim1 dual top-2

    #pragma unroll 2
    for (int g = sub; g < g0; g += 8) {
        const float4 p = v0[g];
        top2_ins(fminf(t - p.x, p.y - t), a1, a2);
        top2_ins(fminf(t - p.z, p.w - t), a3, a4);
    }
    #pragma unroll 2
    for (int g = sub; g < g1; g += 8) {
        const float4 p = v1[g];
        top2_ins(fminf(t - p.x, p.y - t), c1, c2);
        top2_ins(fminf(t - p.z, p.w - t), c3, c4);
    }
    top2_merge(a3, a4, a1, a2);
    top2_merge(c3, c4, c1, c2);

    // ---- octet merge via shfl_xor (all threads participate) ----
    #pragma unroll
    for (int ofs = 1; ofs < 8; ofs <<= 1) {
        const float h1a = __shfl_xor_sync(FULL_, a1, ofs);
        const float h2a = __shfl_xor_sync(FULL_, a2, ofs);
        top2_merge(h1a, h2a, a1, a2);
        const float h1c = __shfl_xor_sync(FULL_, c1, ofs);
        const float h2c = __shfl_xor_sync(FULL_, c2, ofs);
        top2_merge(h1c, h2c, c1, c2);
    }

    if (sub == 0 && tl < TPC_) {
        float* o = out + (size_t)b * (2 * T_ * 2) + tg * 2;
        *reinterpret_cast<float2*>(o)          = make_float2(a1, a2);
        *reinterpret_cast<float2*>(o + T_ * 2) = make_float2(c1, c2);
    }
}

extern "C" void kernel_launch(void* const* d_in, const int* in_sizes, int n_in,
                              void* d_out, int out_size) {
    const float* x    = (const float*)d_in[0];
    const int*   bloc = (const int*)  d_in[1];
    const int*   dloc = (const int*)  d_in[2];
    const int*   didx = (const int*)  d_in[3];
    float*       out  = (float*)      d_out;

    scaled_pl_kernel<<<2 * B_, 512>>>(x, bloc, dloc, didx, out);
}

// round 11
// speedup vs baseline: 1.1198x; 1.1198x over previous
#include <cuda_runtime.h>

// ScaledPLLayer: persistence landscape from precomputed PH pairs.
//   x: [B=64, HW=4096] f32; birth_loc/death_loc/dim_idx: [B,128] i32
//   out: [B, 2, T=100, K=2] f32
//
// out[b,d,t,k] = k-th largest of {max(min(t-birth_n, death_n-t),0) : dim_n==d}
// == top-2 with 0-init over raw tent values of dim-d pairs (order-invariant).
//
// Final structure (best measured: 6.176us; grid = 2 CTAs/sample, block = 512):
//  - Phase 0 (parallel): all threads stage the 16KB x-row into smem
//    (coalesced LDG.128 -> minimal L1tex wavefronts; beats any scattered-L2
//    gather scheme, measured R2/R6); warp 0 loads index arrays AND computes
//    the full ballot partition (positions/counts/sentinel padding — all
//    independent of gathered values, fully overlapped with staging latency).
//  - BAR1; warp 0 only: 8 pipelined LDS gathers + 4 scatter STS into packed
//    s0 (dim0) / s1 (dim1) value arrays, padded to a 16-pair multiple with
//    sentinel (4,-4): tent < 0 everywhere -> no-op under 0-init top-2.
//  - BAR2; octet of threads per t: float4 loads (2 pairs/LDS, broadcast,
//    conflict-free), dual accumulator pairs (6 ops/pair), exact trip counts.
//  - 3-round shfl_xor top-2 merge (measured best; REDUX variant regressed);
//    sub 0 stores 2x float2.

#define B_    64
#define HW_   4096
#define NPH_  128
#define T_    100
#define TPC_  50
#define FULL_ 0xffffffffu

__device__ __forceinline__ void top2_ins(float v, float& m1, float& m2) {
    m2 = fmaxf(m2, fminf(m1, v));
    m1 = fmaxf(m1, v);
}
// merge sorted pair (h1>=h2) into (m1>=m2)
__device__ __forceinline__ void top2_merge(float h1, float h2, float& m1, float& m2) {
    m2 = fmaxf(fminf(m1, h1), fmaxf(m2, h2));
    m1 = fmaxf(m1, h1);
}

__global__ __launch_bounds__(512, 2)
void scaled_pl_kernel(const float* __restrict__ x,
                      const int*   __restrict__ bloc,
                      const int*   __restrict__ dloc,
                      const int*   __restrict__ didx,
                      float*       __restrict__ out) {
    __shared__ __align__(16) float  sx[HW_];        // 16 KB sample row
    __shared__ __align__(16) float2 s0[NPH_ + 16];  // dim0 value pairs
    __shared__ __align__(16) float2 s1[NPH_ + 16];  // dim1 value pairs
    __shared__ int s_n0r, s_n1r;

    const int b     = blockIdx.x >> 1;
    const int thalf = blockIdx.x & 1;
    const int tid   = threadIdx.x;

    // ---- phase 0a: stage x row (all 512 threads, 2x LDG.128 each) ----
    {
        const float4* xb4 = (const float4*)(x + b * HW_);
        float4* sx4 = (float4*)sx;
        const float4 v0 = __ldg(xb4 + tid);
        const float4 v1 = __ldg(xb4 + tid + 512);
        sx4[tid]       = v0;
        sx4[tid + 512] = v1;
    }

    // ---- phase 0b: warp 0 — index loads + FULL partition (no sx needed) ----
    int biv[4], div_[4], pos[4];
    bool is0f[4];
    if (tid < 32) {
        const int lane = tid;
        const int4 bi = __ldg((const int4*)(bloc + b * NPH_) + lane);
        const int4 di = __ldg((const int4*)(dloc + b * NPH_) + lane);
        const int4 dm = __ldg((const int4*)(didx + b * NPH_) + lane);
        biv[0] = bi.x; biv[1] = bi.y; biv[2] = bi.z; biv[3] = bi.w;
        div_[0] = di.x; div_[1] = di.y; div_[2] = di.z; div_[3] = di.w;
        const int dmv[4] = { dm.x, dm.y, dm.z, dm.w };

        const unsigned lt = (1u << lane) - 1u;
        int off0 = 0, off1 = 0;
        #pragma unroll
        for (int p = 0; p < 4; ++p) {
            const bool is0 = (dmv[p] == 0);
            const unsigned mb = __ballot_sync(FULL_, is0);
            const int c0 = __popc(mb);
            is0f[p] = is0;
            pos[p]  = is0 ? (off0 + __popc(mb & lt))
                          : (off1 + __popc(~mb & lt));
            off0 += c0;
            off1 += 32 - c0;
        }
        // sentinel padding to a multiple of 16 pairs (pre-BAR: pad slots are
        // disjoint from the value-scatter slots)
        const int n0r = (off0 + 15) & ~15;
        const int n1r = (off1 + 15) & ~15;
        if (off0 + lane < n0r) s0[off0 + lane] = make_float2(4.0f, -4.0f);
        if (off1 + lane < n1r) s1[off1 + lane] = make_float2(4.0f, -4.0f);
        if (lane == 0) { s_n0r = n0r; s_n1r = n1r; }
    }
    __syncthreads();

    // ---- phase 1: warp 0 — 8 pipelined LDS gathers + 4 scatters ----
    if (tid < 32) {
        float fb[4], fd[4];
        #pragma unroll
        for (int p = 0; p < 4; ++p) { fb[p] = sx[biv[p]]; fd[p] = sx[div_[p]]; }
        #pragma unroll
        for (int p = 0; p < 4; ++p) {
            (is0f[p] ? s0 : s1)[pos[p]] = make_float2(fb[p], fd[p]);
        }
    }
    __syncthreads();

    // ---- phase 2: octet per t, float4 loads, dual accumulators ----
    const int tl  = tid >> 3;            // 0..63
    const int sub = tid & 7;
    const int tg  = thalf * TPC_ + tl;
    const float t = (float)tg * (1.0f / (float)(T_ - 1));

    const int g0 = s_n0r >> 1;           // #float4 groups, multiple of 8
    const int g1 = s_n1r >> 1;
    const float4* v0 = (const float4*)s0;
    const float4* v1 = (const float4*)s1;

    float a1 = 0.f, a2 = 0.f, a3 = 0.f, a4 = 0.f;   // dim0 dual top-2
    float c1 = 0.f, c2 = 0.f, c3 = 0.f, c4 = 0.f;   // dim1 dual top-2

    #pragma unroll 2
    for (int g = sub; g < g0; g += 8) {
        const float4 p = v0[g];
        top2_ins(fminf(t - p.x, p.y - t), a1, a2);
        top2_ins(fminf(t - p.z, p.w - t), a3, a4);
    }
    #pragma unroll 2
    for (int g = sub; g < g1; g += 8) {
        const float4 p = v1[g];
        top2_ins(fminf(t - p.x, p.y - t), c1, c2);
        top2_ins(fminf(t - p.z, p.w - t), c3, c4);
    }
    top2_merge(a3, a4, a1, a2);
    top2_merge(c3, c4, c1, c2);

    // ---- octet merge via shfl_xor (all threads participate) ----
    #pragma unroll
    for (int ofs = 1; ofs < 8; ofs <<= 1) {
        const float h1a = __shfl_xor_sync(FULL_, a1, ofs);
        const float h2a = __shfl_xor_sync(FULL_, a2, ofs);
        top2_merge(h1a, h2a, a1, a2);
        const float h1c = __shfl_xor_sync(FULL_, c1, ofs);
        const float h2c = __shfl_xor_sync(FULL_, c2, ofs);
        top2_merge(h1c, h2c, c1, c2);
    }

    if (sub == 0 && tl < TPC_) {
        float* o = out + (size_t)b * (2 * T_ * 2) + tg * 2;
        *reinterpret_cast<float2*>(o)          = make_float2(a1, a2);
        *reinterpret_cast<float2*>(o + T_ * 2) = make_float2(c1, c2);
    }
}

extern "C" void kernel_launch(void* const* d_in, const int* in_sizes, int n_in,
                              void* d_out, int out_size) {
    const float* x    = (const float*)d_in[0];
    const int*   bloc = (const int*)  d_in[1];
    const int*   dloc = (const int*)  d_in[2];
    const int*   didx = (const int*)  d_in[3];
    float*       out  = (float*)      d_out;

    scaled_pl_kernel<<<2 * B_, 512>>>(x, bloc, dloc, didx, out);
}